// round 2
// baseline (speedup 1.0000x reference)
#include <cuda_runtime.h>
#include <cuda_bf16.h>

// Dual marching cubes, GRID=192, ISO=0.  Fused single-launch version.
// Output (float32, concatenated, reference order):
//   verts  [193^3 * 3]       at V_OFF  = 0
//   vmask  [193^3]           at VM_OFF = 21,567,171
//   quads  [3*193*192*192*4] at Q_OFF  = 28,756,228   (16B-aligned)
//   qmask  [3*193*192*192]   at QM_OFF = 114,133,252  (16B-aligned)

#define GD   192
#define C    193            // cells per axis
#define NC   (C*C*C)        // 7,189,057 cells
#define NEX  (C*GD*GD)      // 7,114,752 edges per direction
#define NQ   (3*NEX)        // 21,344,256 quads
#define V_OFF  0
#define VM_OFF (3*NC)
#define Q_OFF  (VM_OFF + NC)
#define QM_OFF (Q_OFF + 4*NQ)

// quads: each block handles 1024 edges (4/thread), NEX % 1024 == 0
#define QB_PER_DIR (NEX / 1024)   // 6948
#define NQB (3 * QB_PER_DIR)      // 20844
#define NVB ((NC + 255) / 256)    // 28083

// P-coordinate sign: P[i,j,k] = grid[i-1,j-1,k-1] when 1<=i,j,k<=192, else +1.0 (sgn=false)
__device__ __forceinline__ bool sgnP(const float* __restrict__ g, int i, int j, int k) {
    if ((unsigned)(i - 1) < (unsigned)GD &&
        (unsigned)(j - 1) < (unsigned)GD &&
        (unsigned)(k - 1) < (unsigned)GD)
        return __ldg(g + ((i - 1) * GD + (j - 1)) * GD + (k - 1)) < 0.0f;
    return false;
}

__device__ __forceinline__ float fcid(int x, int y, int z) {
    return (float)((x * C + y) * C + z);   // < 193^3 < 2^24, exact in fp32
}

__device__ __forceinline__ void do_quads(const float* __restrict__ g,
                                         float* __restrict__ out, int blk)
{
    const int dir = blk / QB_PER_DIR;
    const int r0  = (blk - dir * QB_PER_DIR) * 1024 + threadIdx.x * 4;

    float4 qm;
    float* qmf = &qm.x;
    float4* qbase = (float4*)(out + Q_OFF) + (size_t)dir * NEX;

    #pragma unroll
    for (int i = 0; i < 4; i++) {
        const int r = r0 + i;
        bool m;
        float4 q;
        if (dir == 0) {
            // x-edges: (193,192,192) over (a, b-1, c-1); b,c in [1,192]
            int a   = r / (GD * GD);
            int rem = r - a * (GD * GD);
            int b   = rem / GD + 1;
            int c   = rem % GD + 1;
            m = sgnP(g, a, b, c) != sgnP(g, a + 1, b, c);
            q = make_float4(fcid(a, b - 1, c - 1), fcid(a, b, c - 1), fcid(a, b, c), fcid(a, b - 1, c));
        } else if (dir == 1) {
            // y-edges: (192,193,192) over (a-1, b, c-1); a,c in [1,192]
            int a   = r / (C * GD) + 1;
            int rem = r % (C * GD);
            int b   = rem / GD;
            int c   = rem % GD + 1;
            m = sgnP(g, a, b, c) != sgnP(g, a, b + 1, c);
            q = make_float4(fcid(a - 1, b, c - 1), fcid(a, b, c - 1), fcid(a, b, c), fcid(a - 1, b, c));
        } else {
            // z-edges: (192,192,193) over (a-1, b-1, c); a,b in [1,192]
            int a   = r / (GD * C) + 1;
            int rem = r % (GD * C);
            int b   = rem / C + 1;
            int c   = rem % C;
            m = sgnP(g, a, b, c) != sgnP(g, a, b, c + 1);
            q = make_float4(fcid(a - 1, b - 1, c), fcid(a, b - 1, c), fcid(a, b, c), fcid(a - 1, b, c));
        }
        __stcs(qbase + r, q);
        qmf[i] = m ? 1.0f : 0.0f;
    }
    __stcs((float4*)(out + QM_OFF + (size_t)dir * NEX + r0), qm);
}

__device__ __forceinline__ void do_verts(const float* __restrict__ g,
                                         float* __restrict__ out, int blk)
{
    __shared__ float s[256 * 3];
    const int tid  = threadIdx.x;
    const int base = blk * 256;
    const int idx  = base + tid;
    const bool active = idx < NC;
    const int cidx = active ? idx : (NC - 1);

    // idx = (a*C + b)*C + c
    int c  = cidx % C;
    int t2 = cidx / C;
    int b  = t2 % C;
    int a  = t2 / C;

    float v[8];
    const int ga = a - 1, gb = b - 1, gc = c - 1;
    const bool interior = (a >= 1) & (a <= GD - 1) & (b >= 1) & (b <= GD - 1) & (c >= 1) & (c <= GD - 1);
    if (interior) {
        const float* p = g + ((ga * GD + gb) * GD + gc);
        #pragma unroll
        for (int k = 0; k < 8; k++) {
            int dx = k & 1, dy = (k >> 1) & 1, dz = (k >> 2) & 1;
            v[k] = __ldg(p + (dx * GD + dy) * GD + dz);
        }
    } else {
        #pragma unroll
        for (int k = 0; k < 8; k++) {
            int x = ga + (k & 1), y = gb + ((k >> 1) & 1), z = gc + ((k >> 2) & 1);
            bool in = ((unsigned)x < (unsigned)GD) & ((unsigned)y < (unsigned)GD) & ((unsigned)z < (unsigned)GD);
            v[k] = in ? __ldg(g + (x * GD + y) * GD + z) : 1.0f;
        }
    }

    // 12 edges: A-corner index, axis; B = A + (1<<axis)
    const int EA[12] = {0,2,4,6, 0,1,4,5, 0,1,2,3};
    float sx = 0.f, sy = 0.f, sz = 0.f, cnt = 0.f;
    #pragma unroll
    for (int e = 0; e < 12; e++) {
        int axis = e >> 2;
        int A = EA[e];
        int B = A + (1 << axis);
        float vA = v[A], vB = v[B];
        bool m = (vA < 0.0f) != (vB < 0.0f);
        if (m) {
            float tt = __fdividef(vA, vA - vB);   // == (0 - vA)/(vB - vA)
            float px = (axis == 0) ? tt : (float)(A & 1);
            float py = (axis == 1) ? tt : (float)((A >> 1) & 1);
            float pz = (axis == 2) ? tt : (float)((A >> 2) & 1);
            sx += px; sy += py; sz += pz; cnt += 1.0f;
        }
    }

    const float inv = __fdividef(1.0f, fmaxf(cnt, 1.0f));
    const float nrm = 1.0f / (float)(GD - 1);
    float fx = ((float)a + sx * inv - 1.0f) * nrm;
    float fy = ((float)b + sy * inv - 1.0f) * nrm;
    float fz = ((float)c + sz * inv - 1.0f) * nrm;

    // stage stride-3 writes via smem -> unit-stride coalesced streaming stores
    s[tid * 3 + 0] = fx;
    s[tid * 3 + 1] = fy;
    s[tid * 3 + 2] = fz;
    __syncthreads();
    const int outb = base * 3;
    #pragma unroll
    for (int i = 0; i < 3; i++) {
        int o = outb + tid + i * 256;
        if (o < 3 * NC) __stcs(out + V_OFF + o, s[tid + i * 256]);
    }
    if (active) __stcs(out + VM_OFF + idx, (cnt > 0.0f) ? 1.0f : 0.0f);
}

__global__ void __launch_bounds__(256)
dmc_fused(const float* __restrict__ g, float* __restrict__ out)
{
    if (blockIdx.x < NQB)
        do_quads(g, out, blockIdx.x);
    else
        do_verts(g, out, blockIdx.x - NQB);
}

extern "C" void kernel_launch(void* const* d_in, const int* in_sizes, int n_in,
                              void* d_out, int out_size)
{
    const float* g = (const float*)d_in[0];
    float* out = (float*)d_out;
    dmc_fused<<<NQB + NVB, 256>>>(g, out);
}

// round 3
// speedup vs baseline: 1.9536x; 1.9536x over previous
#include <cuda_runtime.h>
#include <cuda_bf16.h>

// Dual marching cubes, GRID=192, ISO=0. Single kernel, 1 thread = 1 cell + 3 edges.
// Output (float32, concatenated, reference order):
//   verts  [193^3 * 3]       at V_OFF  = 0
//   vmask  [193^3]           at VM_OFF = 21,567,171
//   quads  [3*193*192*192*4] at Q_OFF  = 28,756,228   (16B-aligned)
//   qmask  [3*193*192*192]   at QM_OFF = 114,133,252  (16B-aligned)

#define GD   192
#define C    193            // cells per axis
#define NC   (C*C*C)        // 7,189,057 cells
#define NEX  (C*GD*GD)      // 7,114,752 edges per direction
#define NQ   (3*NEX)        // 21,344,256 quads
#define V_OFF  0
#define VM_OFF (3*NC)
#define Q_OFF  (VM_OFF + NC)
#define QM_OFF (Q_OFF + 4*NQ)
#define NVB ((NC + 255) / 256)    // 28083 blocks

// P-coordinate sign: P[i,j,k] = grid[i-1,j-1,k-1] when 1<=i,j,k<=192, else +1.0 (false)
__device__ __forceinline__ bool sgnP(const float* __restrict__ g, int i, int j, int k) {
    if ((unsigned)(i - 1) < (unsigned)GD &&
        (unsigned)(j - 1) < (unsigned)GD &&
        (unsigned)(k - 1) < (unsigned)GD)
        return __ldg(g + ((i - 1) * GD + (j - 1)) * GD + (k - 1)) < 0.0f;
    return false;
}

__device__ __forceinline__ float fcid(int x, int y, int z) {
    return (float)((x * C + y) * C + z);   // < 193^3 < 2^24, exact in fp32
}

__global__ void __launch_bounds__(256)
dmc_all(const float* __restrict__ g, float* __restrict__ out)
{
    __shared__ float s[256 * 3];
    const int tid  = threadIdx.x;
    const int base = blockIdx.x * 256;
    const int idx  = base + tid;

    // ------------------------------------------------------------------ verts
    {
        const bool active = idx < NC;
        const int cidx = active ? idx : (NC - 1);

        // idx = (a*C + b)*C + c
        int c  = cidx % C;
        int t2 = cidx / C;
        int b  = t2 % C;
        int a  = t2 / C;

        float v[8];
        const int ga = a - 1, gb = b - 1, gc = c - 1;
        const bool interior = (a >= 1) & (a <= GD - 1) & (b >= 1) & (b <= GD - 1) & (c >= 1) & (c <= GD - 1);
        if (interior) {
            const float* p = g + ((ga * GD + gb) * GD + gc);
            #pragma unroll
            for (int k = 0; k < 8; k++) {
                int dx = k & 1, dy = (k >> 1) & 1, dz = (k >> 2) & 1;
                v[k] = __ldg(p + (dx * GD + dy) * GD + dz);
            }
        } else {
            #pragma unroll
            for (int k = 0; k < 8; k++) {
                int x = ga + (k & 1), y = gb + ((k >> 1) & 1), z = gc + ((k >> 2) & 1);
                bool in = ((unsigned)x < (unsigned)GD) & ((unsigned)y < (unsigned)GD) & ((unsigned)z < (unsigned)GD);
                v[k] = in ? __ldg(g + (x * GD + y) * GD + z) : 1.0f;
            }
        }

        // 12 edges: A-corner index, axis; B = A + (1<<axis)
        const int EA[12] = {0,2,4,6, 0,1,4,5, 0,1,2,3};
        float sx = 0.f, sy = 0.f, sz = 0.f, cnt = 0.f;
        #pragma unroll
        for (int e = 0; e < 12; e++) {
            int axis = e >> 2;
            int A = EA[e];
            int B = A + (1 << axis);
            float vA = v[A], vB = v[B];
            bool m = (vA < 0.0f) != (vB < 0.0f);
            if (m) {
                float tt = __fdividef(vA, vA - vB);   // == (0 - vA)/(vB - vA)
                float px = (axis == 0) ? tt : (float)(A & 1);
                float py = (axis == 1) ? tt : (float)((A >> 1) & 1);
                float pz = (axis == 2) ? tt : (float)((A >> 2) & 1);
                sx += px; sy += py; sz += pz; cnt += 1.0f;
            }
        }

        const float inv = __fdividef(1.0f, fmaxf(cnt, 1.0f));
        const float nrm = 1.0f / (float)(GD - 1);
        float fx = ((float)a + sx * inv - 1.0f) * nrm;
        float fy = ((float)b + sy * inv - 1.0f) * nrm;
        float fz = ((float)c + sz * inv - 1.0f) * nrm;

        // stage stride-3 writes via smem -> unit-stride coalesced streaming stores
        s[tid * 3 + 0] = fx;
        s[tid * 3 + 1] = fy;
        s[tid * 3 + 2] = fz;
        __syncthreads();
        const int outb = base * 3;
        #pragma unroll
        for (int i = 0; i < 3; i++) {
            int o = outb + tid + i * 256;
            if (o < 3 * NC) __stcs(out + V_OFF + o, s[tid + i * 256]);
        }
        if (active) __stcs(out + VM_OFF + idx, (cnt > 0.0f) ? 1.0f : 0.0f);
    }

    // ------------------------------------------------------------------ quads
    // one edge per direction at the same flat index -> all stores lane-coalesced
    if (idx < NEX) {
        const int r = idx;
        float4* qbase = (float4*)(out + Q_OFF);

        // dir 0: x-edges, shape (193,192,192) over (a, b-1, c-1); b,c in [1,192]
        {
            int a   = r / (GD * GD);
            int rem = r - a * (GD * GD);
            int b   = rem / GD + 1;
            int c   = rem % GD + 1;
            bool m = sgnP(g, a, b, c) != sgnP(g, a + 1, b, c);
            float4 q = make_float4(fcid(a, b - 1, c - 1), fcid(a, b, c - 1),
                                   fcid(a, b, c),         fcid(a, b - 1, c));
            __stcs(qbase + r, q);
            __stcs(out + QM_OFF + r, m ? 1.0f : 0.0f);
        }
        // dir 1: y-edges, shape (192,193,192) over (a-1, b, c-1); a,c in [1,192]
        {
            int a   = r / (C * GD) + 1;
            int rem = r % (C * GD);
            int b   = rem / GD;
            int c   = rem % GD + 1;
            bool m = sgnP(g, a, b, c) != sgnP(g, a, b + 1, c);
            float4 q = make_float4(fcid(a - 1, b, c - 1), fcid(a, b, c - 1),
                                   fcid(a, b, c),         fcid(a - 1, b, c));
            __stcs(qbase + NEX + r, q);
            __stcs(out + QM_OFF + NEX + r, m ? 1.0f : 0.0f);
        }
        // dir 2: z-edges, shape (192,192,193) over (a-1, b-1, c); a,b in [1,192]
        {
            int a   = r / (GD * C) + 1;
            int rem = r % (GD * C);
            int b   = rem / C + 1;
            int c   = rem % C;
            bool m = sgnP(g, a, b, c) != sgnP(g, a, b, c + 1);
            float4 q = make_float4(fcid(a - 1, b - 1, c), fcid(a, b - 1, c),
                                   fcid(a, b, c),         fcid(a - 1, b, c));
            __stcs(qbase + 2 * NEX + r, q);
            __stcs(out + QM_OFF + 2 * NEX + r, m ? 1.0f : 0.0f);
        }
    }
}

extern "C" void kernel_launch(void* const* d_in, const int* in_sizes, int n_in,
                              void* d_out, int out_size)
{
    const float* g = (const float*)d_in[0];
    float* out = (float*)d_out;
    dmc_all<<<NVB, 256>>>(g, out);
}

// round 4
// speedup vs baseline: 2.3073x; 1.1811x over previous
#include <cuda_runtime.h>
#include <cuda_bf16.h>

// Dual marching cubes, GRID=192, ISO=0. One thread = one cell: vertex + the
// x/y/z grid edges at the cell's own P-coordinate (signs reuse the corner loads).
// Output (float32, concatenated, reference order):
//   verts  [193^3 * 3]       at V_OFF  = 0
//   vmask  [193^3]           at VM_OFF = 21,567,171
//   quads  [3*193*192*192*4] at Q_OFF  = 28,756,228   (16B-aligned)
//   qmask  [3*193*192*192]   at QM_OFF = 114,133,252  (16B-aligned)

#define GD   192
#define C    193            // cells per axis
#define C2   (C*C)          // 37249
#define NC   (C*C*C)        // 7,189,057 cells
#define NEX  (C*GD*GD)      // 7,114,752 edges per direction
#define NQ   (3*NEX)        // 21,344,256 quads
#define V_OFF  0
#define VM_OFF (3*NC)
#define Q_OFF  (VM_OFF + NC)
#define QM_OFF (Q_OFF + 4*NQ)
#define NVB ((NC + 255) / 256)    // 28083 blocks

__global__ void __launch_bounds__(256)
dmc_all(const float* __restrict__ g, float* __restrict__ out)
{
    __shared__ float s[256 * 3];
    const int tid  = threadIdx.x;
    const int base = blockIdx.x * 256;
    const int idx  = base + tid;
    const bool active = idx < NC;
    const int cidx = active ? idx : (NC - 1);

    // cidx = (a*C + b)*C + c ; P-coordinate of this cell's min corner is (a,b,c)
    int c  = cidx % C;
    int t2 = cidx / C;
    int b  = t2 % C;
    int a  = t2 / C;

    // corner k: dx=k&1, dy=(k>>1)&1, dz=(k>>2)&1 ; P[a+dx, b+dy, c+dz]
    float v[8];
    const int ga = a - 1, gb = b - 1, gc = c - 1;
    const bool interior = (a >= 1) & (a <= GD - 1) & (b >= 1) & (b <= GD - 1) & (c >= 1) & (c <= GD - 1);
    if (interior) {
        const float* p = g + ((ga * GD + gb) * GD + gc);
        #pragma unroll
        for (int k = 0; k < 8; k++) {
            int dx = k & 1, dy = (k >> 1) & 1, dz = (k >> 2) & 1;
            v[k] = __ldg(p + (dx * GD + dy) * GD + dz);
        }
    } else {
        #pragma unroll
        for (int k = 0; k < 8; k++) {
            int x = ga + (k & 1), y = gb + ((k >> 1) & 1), z = gc + ((k >> 2) & 1);
            bool in = ((unsigned)x < (unsigned)GD) & ((unsigned)y < (unsigned)GD) & ((unsigned)z < (unsigned)GD);
            v[k] = in ? __ldg(g + (x * GD + y) * GD + z) : 1.0f;   // pad value iso+1
        }
    }

    // ------------------------------------------------------------------ vertex
    // 12 edges: A-corner index, axis; B = A + (1<<axis)
    const int EA[12] = {0,2,4,6, 0,1,4,5, 0,1,2,3};
    float sx = 0.f, sy = 0.f, sz = 0.f, cnt = 0.f;
    #pragma unroll
    for (int e = 0; e < 12; e++) {
        int axis = e >> 2;
        int A = EA[e];
        int B = A + (1 << axis);
        float vA = v[A], vB = v[B];
        bool m = (vA < 0.0f) != (vB < 0.0f);
        if (m) {
            float tt = __fdividef(vA, vA - vB);   // == (0 - vA)/(vB - vA)
            float px = (axis == 0) ? tt : (float)(A & 1);
            float py = (axis == 1) ? tt : (float)((A >> 1) & 1);
            float pz = (axis == 2) ? tt : (float)((A >> 2) & 1);
            sx += px; sy += py; sz += pz; cnt += 1.0f;
        }
    }

    const float inv = __fdividef(1.0f, fmaxf(cnt, 1.0f));
    const float nrm = 1.0f / (float)(GD - 1);
    float fx = ((float)a + sx * inv - 1.0f) * nrm;
    float fy = ((float)b + sy * inv - 1.0f) * nrm;
    float fz = ((float)c + sz * inv - 1.0f) * nrm;

    // stage stride-3 writes via smem -> unit-stride coalesced streaming stores
    s[tid * 3 + 0] = fx;
    s[tid * 3 + 1] = fy;
    s[tid * 3 + 2] = fz;
    __syncthreads();
    const int outb = base * 3;
    #pragma unroll
    for (int i = 0; i < 3; i++) {
        int o = outb + tid + i * 256;
        if (o < 3 * NC) __stcs(out + V_OFF + o, s[tid + i * 256]);
    }
    if (active) __stcs(out + VM_OFF + idx, (cnt > 0.0f) ? 1.0f : 0.0f);

    // ------------------------------------------------------------------ quads
    // Edge signs are corner values: sgnP(a,b,c)=v0, (a+1,b,c)=v1, (a,b+1,c)=v2, (a,b,c+1)=v4.
    // Quad cell-ids are idx +- compile-time constants (exact in fp32, idx < 2^23).
    if (active) {
        const bool s0 = v[0] < 0.0f, s1 = v[1] < 0.0f, s2v = v[2] < 0.0f, s4 = v[4] < 0.0f;
        const float fb = (float)cidx;
        float4* qb = (float4*)(out + Q_OFF);

        // x-edge (a,b,c): valid for b>=1, c>=1 ; out flat = (a*192 + b-1)*192 + (c-1)
        if ((b >= 1) & (c >= 1)) {
            int o0 = (a * GD + b - 1) * GD + (c - 1);
            __stcs(qb + o0, make_float4(fb - (float)(C + 1), fb - 1.0f, fb, fb - (float)C));
            __stcs(out + QM_OFF + o0, (s0 != s1) ? 1.0f : 0.0f);
        }
        // y-edge (a,b,c): valid for a>=1, c>=1 ; out flat = ((a-1)*193 + b)*192 + (c-1)
        if ((a >= 1) & (c >= 1)) {
            int o1 = (t2 - C) * GD + (c - 1);
            __stcs(qb + NEX + o1, make_float4(fb - (float)(C2 + 1), fb - 1.0f, fb, fb - (float)C2));
            __stcs(out + QM_OFF + NEX + o1, (s0 != s2v) ? 1.0f : 0.0f);
        }
        // z-edge (a,b,c): valid for a>=1, b>=1 ; out flat = ((a-1)*192 + b-1)*193 + c
        if ((a >= 1) & (b >= 1)) {
            int o2 = (a * GD + b - C) * C + c;
            __stcs(qb + 2 * NEX + o2, make_float4(fb - (float)(C2 + C), fb - (float)C, fb, fb - (float)C2));
            __stcs(out + QM_OFF + 2 * NEX + o2, (s0 != s4) ? 1.0f : 0.0f);
        }
    }
}

extern "C" void kernel_launch(void* const* d_in, const int* in_sizes, int n_in,
                              void* d_out, int out_size)
{
    const float* g = (const float*)d_in[0];
    float* out = (float*)d_out;
    dmc_all<<<NVB, 256>>>(g, out);
}